// round 12
// baseline (speedup 1.0000x reference)
#include <cuda_runtime.h>
#include <cuda_bf16.h>
#include <cstdint>
#include <cstddef>

// ---------------------------------------------------------------------------
// VQ quantizer via mma.sync (HMMA) bf16 triple-split GEMM (fp32-accurate dot).
// Small CTA (64 tok x 64 codes/chunk) -> 2 CTAs/SM for latency hiding.
// ldmatrix loads, TMA bulk streaming, full/empty mbarrier pipeline.
//   z (NT x 64) vs codebook (1024 x 64)
//   outputs (concat f32): e[NT], z_q[NT*64], sim[NT*K], loss[NT]
//   16 warps: warp = (mgrp 0..3) x (ncol 0..3); M=16 x N=16 per warp
// ---------------------------------------------------------------------------

#define D        64
#define BM       64                  // tokens per CTA
#define BN       64                  // codes per chunk
#define KTOT     1024
#define NCHUNK   (KTOT / BN)         // 16
#define THREADS  512

#define ROWB     144u                // padded row: 64 bf16 (128B) + 16B pad
#define SPLIT_A  (64u * ROWB)        // 9216 B per A split tile
#define SPLIT_Bc (64u * ROWB)        // 9216 B per B split tile
#define CHUNK_B  (3u * SPLIT_Bc)     // 27648 B per chunk

#define OFF_A    0u                  // 3 x 9216 = 27648
#define OFF_B0   27648u
#define OFF_B1   55296u
#define OFF_PAIR 82944u              // 8192 B: (en2, einv) float2 per code
#define OFF_ZN   91136u              // 256 B
#define OFF_ZI   91392u              // 256 B
#define OFF_MD   91648u              // 4 x 64 f32
#define OFF_MI   92672u              // 4 x 64 int
#define OFF_MBAR 93696u              // full0, full1, empty0, empty1
#define SMEM_REQ 93760u

__device__ __forceinline__ void ldsm_x4(uint32_t* r, unsigned addr) {
    asm volatile("ldmatrix.sync.aligned.m8n8.x4.shared.b16 {%0,%1,%2,%3}, [%4];"
                 : "=r"(r[0]), "=r"(r[1]), "=r"(r[2]), "=r"(r[3]) : "r"(addr));
}

__device__ __forceinline__ void mma16816(float* d, const uint32_t* a, const uint32_t* b) {
    asm volatile(
        "mma.sync.aligned.m16n8k16.row.col.f32.bf16.bf16.f32 "
        "{%0,%1,%2,%3}, {%4,%5,%6,%7}, {%8,%9}, {%0,%1,%2,%3};"
        : "+f"(d[0]), "+f"(d[1]), "+f"(d[2]), "+f"(d[3])
        : "r"(a[0]), "r"(a[1]), "r"(a[2]), "r"(a[3]), "r"(b[0]), "r"(b[1]));
}

#define MBAR_INIT(addr, cnt) \
    asm volatile("mbarrier.init.shared.b64 [%0], %1;" :: "r"(addr), "r"(cnt) : "memory")
#define MBAR_EXPECT_TX(addr, bytes) \
    asm volatile("mbarrier.arrive.expect_tx.shared.b64 _, [%0], %1;" \
                 :: "r"(addr), "r"(bytes) : "memory")
#define MBAR_ARRIVE(addr) \
    asm volatile("mbarrier.arrive.shared.b64 _, [%0];" :: "r"(addr) : "memory")
#define MBAR_WAIT(addr, ph) \
    asm volatile("{\n\t.reg .pred P;\n\tWL%=:\n\t" \
                 "mbarrier.try_wait.parity.shared.b64 P, [%0], %1;\n\t" \
                 "@!P bra WL%=;\n\t}" :: "r"(addr), "r"(ph) : "memory")
#define BULK_G2S(dst, src, bytes, mbar) \
    asm volatile("cp.async.bulk.shared::cluster.global.mbarrier::complete_tx::bytes " \
                 "[%0], [%1], %2, [%3];" \
                 :: "r"(dst), "l"(src), "r"(bytes), "r"(mbar) : "memory")

// ---------------- prep: norms + padded bf16 split images --------------------
// split layout: [chunk 0..15][split 0..2][row 0..63][dim 0..71(pad)]
__device__ __align__(16) unsigned short g_bsplit[NCHUNK * 3 * 64 * 72];
__device__ __align__(16) float2 g_pairs[KTOT];    // (en2, einv)

__global__ void vq_prep(const float* __restrict__ cbk) {
    int idx = blockIdx.x * blockDim.x + threadIdx.x;   // 0 .. KTOT*D-1
    if (idx >= KTOT * D) return;
    int code = idx >> 6, d = idx & 63;
    int c = code >> 6, r = code & 63;
    float x = cbk[idx];
    __nv_bfloat16 b0 = __float2bfloat16(x);
    float r1 = x - __bfloat162float(b0);
    __nv_bfloat16 b1 = __float2bfloat16(r1);
    float r2 = r1 - __bfloat162float(b1);
    __nv_bfloat16 b2 = __float2bfloat16(r2);
    unsigned basei = (unsigned)(c * 3) * 4608u + (unsigned)r * 72u + (unsigned)d;
    g_bsplit[basei]          = __bfloat16_as_ushort(b0);
    g_bsplit[basei + 4608u]  = __bfloat16_as_ushort(b1);
    g_bsplit[basei + 9216u]  = __bfloat16_as_ushort(b2);

    if (idx < KTOT) {
        const float4* row = reinterpret_cast<const float4*>(cbk + (size_t)idx * D);
        float s = 0.f;
#pragma unroll
        for (int i = 0; i < D / 4; ++i) {
            float4 v = row[i];
            s += v.x * v.x + v.y * v.y + v.z * v.z + v.w * v.w;
        }
        g_pairs[idx] = make_float2(s, rsqrtf(s));
    }
}

// ---------------- main kernel ------------------------------------------------
__global__ void __launch_bounds__(THREADS, 2)
vq_mma_kernel(const float* __restrict__ z,
              const float* __restrict__ cbk,
              float* __restrict__ e_out,
              float* __restrict__ zq_out,
              float* __restrict__ sim_out,
              float* __restrict__ loss_out) {
    extern __shared__ unsigned char smp[];
    unsigned base;
    asm("{ .reg .u64 t; cvta.to.shared.u64 t, %1; cvt.u32.u64 %0, t; }"
        : "=r"(base) : "l"((void*)smp));

    const int tid   = threadIdx.x;
    const int lane  = tid & 31;
    const int warp  = tid >> 5;
    const int quad  = lane >> 2;     // 0..7
    const int qlane = lane & 3;      // 0..3
    const int mgrp  = warp & 3;      // token row group (16 rows)
    const int ncol  = warp >> 2;     // 16-code column group

    float2* pairs  = (float2*)(smp + OFF_PAIR);
    float*  znorms = (float*)(smp + OFF_ZN);
    float*  zinvs  = (float*)(smp + OFF_ZI);
    float*  mindS  = (float*)(smp + OFF_MD);   // [4][64]
    int*    miniS  = (int*)(smp + OFF_MI);     // [4][64]
    const unsigned full0  = base + OFF_MBAR;
    const unsigned full1  = full0 + 8;
    const unsigned empty0 = full0 + 16;
    const unsigned empty1 = full0 + 24;

    if (tid == 0) {
        MBAR_INIT(full0, 1);  MBAR_INIT(full1, 1);
        MBAR_INIT(empty0, THREADS); MBAR_INIT(empty1, THREADS);
    }
    __syncthreads();

    // ---- single-thread bulk loads of B chunks 0 and 1 -------------------
    if (tid == 0) {
        const char* gb = (const char*)g_bsplit;
        MBAR_EXPECT_TX(full0, CHUNK_B);
        BULK_G2S(base + OFF_B0, gb, CHUNK_B, full0);
        MBAR_EXPECT_TX(full1, CHUNK_B);
        BULK_G2S(base + OFF_B1, gb + CHUNK_B, CHUNK_B, full1);
    }

    // ---- (en2, einv) pair table into smem --------------------------------
    for (int k = tid; k < KTOT; k += THREADS) pairs[k] = g_pairs[k];

    // ---- build A split tiles (thread t<64 owns token-row t) -------------
    if (tid < BM) {
        const size_t tok = (size_t)blockIdx.x * BM + tid;
        const float4* zr = reinterpret_cast<const float4*>(z + tok * D);
        float zn = 0.f;
#pragma unroll
        for (int q = 0; q < 16; ++q) {
            float4 v = zr[q];
            zn += v.x * v.x + v.y * v.y + v.z * v.z + v.w * v.w;
            float xs[4] = {v.x, v.y, v.z, v.w};
            unsigned long long p0 = 0, p1 = 0, p2 = 0;
#pragma unroll
            for (int j = 0; j < 4; ++j) {
                float x = xs[j];
                __nv_bfloat16 b0 = __float2bfloat16(x);
                float rr1 = x - __bfloat162float(b0);
                __nv_bfloat16 b1 = __float2bfloat16(rr1);
                float rr2 = rr1 - __bfloat162float(b1);
                __nv_bfloat16 b2 = __float2bfloat16(rr2);
                p0 |= (unsigned long long)__bfloat16_as_ushort(b0) << (16 * j);
                p1 |= (unsigned long long)__bfloat16_as_ushort(b1) << (16 * j);
                p2 |= (unsigned long long)__bfloat16_as_ushort(b2) << (16 * j);
            }
            unsigned off = (unsigned)tid * ROWB + (unsigned)q * 8u;
            *(unsigned long long*)(smp + OFF_A + 0 * SPLIT_A + off) = p0;
            *(unsigned long long*)(smp + OFF_A + 1 * SPLIT_A + off) = p1;
            *(unsigned long long*)(smp + OFF_A + 2 * SPLIT_A + off) = p2;
        }
        znorms[tid] = zn;
        zinvs[tid]  = rsqrtf(zn);
    }
    __syncthreads();     // A tiles + norms visible to all warps

    // this thread's 2 token rows
    const int r0 = mgrp * 16 + quad;
    const int r1 = r0 + 8;
    const float zn0 = znorms[r0], zn1 = znorms[r1];
    const float zi0 = zinvs[r0],  zi1 = zinvs[r1];
    float* sim0 = sim_out + ((size_t)blockIdx.x * BM + r0) * (size_t)KTOT;
    float* sim1 = sim0 + 8 * (size_t)KTOT;

    float mind0 = 3.4e38f, mind1 = 3.4e38f;
    int   mini0 = 0,       mini1 = 0;

    // per-lane ldmatrix offsets
    const unsigned aoff = (unsigned)(lane & 15) * ROWB + (unsigned)((lane >> 4) & 1) * 16u;
    const unsigned aBase = base + OFF_A + (unsigned)(mgrp * 16) * ROWB + aoff;
    const unsigned boff = ((unsigned)(lane & 7) + (unsigned)((lane >> 4) & 1) * 8u) * ROWB
                        + (unsigned)((lane >> 3) & 1) * 16u;
    const unsigned bColOff = (unsigned)(ncol * 16) * ROWB + boff;

#pragma unroll 1
    for (int c = 0; c < NCHUNK; ++c) {
        const int b = c & 1;
        const unsigned ph = (unsigned)((c >> 1) & 1);
        MBAR_WAIT(b ? full1 : full0, ph);

        const unsigned Bb = base + (b ? OFF_B1 : OFF_B0) + bColOff;

        float acc[2][4];     // [n8-group][frag]
#pragma unroll
        for (int nj = 0; nj < 2; ++nj)
#pragma unroll
            for (int j = 0; j < 4; ++j) acc[nj][j] = 0.f;

#pragma unroll
        for (int kk = 0; kk < 4; ++kk) {
            uint32_t A[3][4];
#pragma unroll
            for (int s = 0; s < 3; ++s)
                ldsm_x4(A[s], aBase + (unsigned)s * SPLIT_A + (unsigned)kk * 32u);

#pragma unroll
            for (int sb = 0; sb < 3; ++sb) {
                uint32_t Bf[4];
                ldsm_x4(Bf, Bb + (unsigned)sb * SPLIT_Bc + (unsigned)kk * 32u);

                const int nsa = (sb == 0) ? 3 : (sb == 1) ? 2 : 1;
#pragma unroll
                for (int sa = 0; sa < 3; ++sa) {
                    if (sa < nsa) {
                        mma16816(acc[0], A[sa], &Bf[0]);
                        mma16816(acc[1], A[sa], &Bf[2]);
                    }
                }
            }
        }

        MBAR_ARRIVE(b ? empty1 : empty0);

        if (c + 2 < NCHUNK && tid == 0) {
            MBAR_WAIT(b ? empty1 : empty0, ph);
            const char* gb = (const char*)g_bsplit + (size_t)(c + 2) * CHUNK_B;
            MBAR_EXPECT_TX(b ? full1 : full0, CHUNK_B);
            BULK_G2S(base + (b ? OFF_B1 : OFF_B0), gb, CHUNK_B, b ? full1 : full0);
        }

        // ---- epilogue from registers (overlaps other warps' MMAs) -------
        const int cbase = c * BN + ncol * 16;
#pragma unroll
        for (int nj = 0; nj < 2; ++nj) {
            const int gci = cbase + nj * 8 + qlane * 2;
            float4 pv = *reinterpret_cast<const float4*>(pairs + gci);
            const float d00 = acc[nj][0], d01 = acc[nj][1];
            const float d10 = acc[nj][2], d11 = acc[nj][3];
            float t;
            t = fmaf(-2.f, d00, zn0) + pv.x; if (t < mind0) { mind0 = t; mini0 = gci; }
            t = fmaf(-2.f, d01, zn0) + pv.z; if (t < mind0) { mind0 = t; mini0 = gci + 1; }
            t = fmaf(-2.f, d10, zn1) + pv.x; if (t < mind1) { mind1 = t; mini1 = gci; }
            t = fmaf(-2.f, d11, zn1) + pv.z; if (t < mind1) { mind1 = t; mini1 = gci + 1; }
            __stcs(reinterpret_cast<float2*>(sim0 + gci),
                   make_float2(d00 * zi0 * pv.y, d01 * zi0 * pv.w));
            __stcs(reinterpret_cast<float2*>(sim1 + gci),
                   make_float2(d10 * zi1 * pv.y, d11 * zi1 * pv.w));
        }
    }

    // ---- argmin reduce across qlane --------------------------------------
#pragma unroll
    for (int off = 1; off <= 2; off <<= 1) {
        float od0 = __shfl_xor_sync(0xffffffffu, mind0, off);
        int   oi0 = __shfl_xor_sync(0xffffffffu, mini0, off);
        if (od0 < mind0 || (od0 == mind0 && oi0 < mini0)) { mind0 = od0; mini0 = oi0; }
        float od1 = __shfl_xor_sync(0xffffffffu, mind1, off);
        int   oi1 = __shfl_xor_sync(0xffffffffu, mini1, off);
        if (od1 < mind1 || (od1 == mind1 && oi1 < mini1)) { mind1 = od1; mini1 = oi1; }
    }
    if (qlane == 0) {
        mindS[ncol * 64 + r0] = mind0;  miniS[ncol * 64 + r0] = mini0;
        mindS[ncol * 64 + r1] = mind1;  miniS[ncol * 64 + r1] = mini1;
    }
    __syncthreads();

    // ---- final per-token outputs: e, z_q, loss (fp32 from global) ------
    if (tid < BM) {
        float bd = mindS[tid];
        int   bi = miniS[tid];
#pragma unroll
        for (int s = 1; s < 4; ++s) {
            float d = mindS[s * 64 + tid];
            int   i = miniS[s * 64 + tid];
            if (d < bd || (d == bd && i < bi)) { bd = d; bi = i; }
        }
        const size_t tok = (size_t)blockIdx.x * BM + tid;
        const float4* er = reinterpret_cast<const float4*>(cbk + (size_t)bi * D);
        const float4* zr = reinterpret_cast<const float4*>(z + tok * D);
        float4* zq = reinterpret_cast<float4*>(zq_out + tok * D);
        float s = 0.f;
#pragma unroll
        for (int q = 0; q < 16; ++q) {
            float4 ev = er[q];
            float4 zv = zr[q];
            float dx = zv.x - ev.x, dy = zv.y - ev.y, dz = zv.z - ev.z, dw = zv.w - ev.w;
            s += dx * dx + dy * dy + dz * dz + dw * dw;
            zq[q] = ev;
        }
        loss_out[tok] = 1.25f * sqrtf(s);
        e_out[tok]    = (float)bi;
    }
}

extern "C" void kernel_launch(void* const* d_in, const int* in_sizes, int n_in,
                              void* d_out, int out_size) {
    const float* z   = (const float*)d_in[0];
    const float* cbk = (const float*)d_in[1];
    const int NT = in_sizes[0] / D;    // 131072

    float* out      = (float*)d_out;
    float* e_out    = out;
    float* zq_out   = e_out + NT;
    float* sim_out  = zq_out + (size_t)NT * D;
    float* loss_out = sim_out + (size_t)NT * KTOT;

    vq_prep<<<(KTOT * D + 255) / 256, 256>>>(cbk);

    cudaFuncSetAttribute(vq_mma_kernel, cudaFuncAttributeMaxDynamicSharedMemorySize, SMEM_REQ);
    vq_mma_kernel<<<NT / BM, THREADS, SMEM_REQ>>>(z, cbk, e_out, zq_out, sim_out, loss_out);
}

// round 13
// speedup vs baseline: 1.1158x; 1.1158x over previous
#include <cuda_runtime.h>
#include <cuda_bf16.h>
#include <cstdint>
#include <cstddef>

// ---------------------------------------------------------------------------
// VQ quantizer via mma.sync (HMMA) bf16 triple-split GEMM (fp32-accurate dot).
// M32xN32 warp tiles; ldmatrix loads; TMA bulk streaming with THREE B buffers
// (deep pipeline, warps free-run ~2 chunks); pair norms prefetched via LDG.
//   z (NT x 64) vs codebook (1024 x 64)
//   outputs (concat f32): e[NT], z_q[NT*64], sim[NT*K], loss[NT]
//   16 warps: warp = (mgrp 0..3) x (ncol 0..3); M=32 x N=32 per warp
// ---------------------------------------------------------------------------

#define D        64
#define BM       128                 // tokens per CTA
#define BN       128                 // codes per chunk
#define KTOT     1024
#define NCHUNK   (KTOT / BN)         // 8
#define NBUF     3
#define THREADS  512

#define ROWB     144u                // padded row: 64 bf16 (128B) + 16B pad
#define SPLIT_B  (128u * ROWB)       // 18432 B per split tile
#define CHUNK_B  (3u * SPLIT_B)      // 55296 B per chunk (3 splits)

#define OFF_A    0u                  // A splits: 3 x 18432 = 55296
#define OFF_B    55296u              // 3 buffers x 55296 = 165888
#define OFF_ZN   221184u             // 512 B
#define OFF_ZI   221696u             // 512 B
#define OFF_MD   222208u             // 4 x 128 f32 = 2048
#define OFF_MI   224256u             // 4 x 128 int = 2048
#define OFF_MBAR 226304u             // full0..2, empty0..2 (6 x 8 B)
#define SMEM_REQ 226368u

__device__ __forceinline__ void ldsm_x4(uint32_t* r, unsigned addr) {
    asm volatile("ldmatrix.sync.aligned.m8n8.x4.shared.b16 {%0,%1,%2,%3}, [%4];"
                 : "=r"(r[0]), "=r"(r[1]), "=r"(r[2]), "=r"(r[3]) : "r"(addr));
}

__device__ __forceinline__ void mma16816(float* d, const uint32_t* a, const uint32_t* b) {
    asm volatile(
        "mma.sync.aligned.m16n8k16.row.col.f32.bf16.bf16.f32 "
        "{%0,%1,%2,%3}, {%4,%5,%6,%7}, {%8,%9}, {%0,%1,%2,%3};"
        : "+f"(d[0]), "+f"(d[1]), "+f"(d[2]), "+f"(d[3])
        : "r"(a[0]), "r"(a[1]), "r"(a[2]), "r"(a[3]), "r"(b[0]), "r"(b[1]));
}

#define MBAR_INIT(addr, cnt) \
    asm volatile("mbarrier.init.shared.b64 [%0], %1;" :: "r"(addr), "r"(cnt) : "memory")
#define MBAR_EXPECT_TX(addr, bytes) \
    asm volatile("mbarrier.arrive.expect_tx.shared.b64 _, [%0], %1;" \
                 :: "r"(addr), "r"(bytes) : "memory")
#define MBAR_ARRIVE(addr) \
    asm volatile("mbarrier.arrive.shared.b64 _, [%0];" :: "r"(addr) : "memory")
#define MBAR_WAIT(addr, ph) \
    asm volatile("{\n\t.reg .pred P;\n\tWL%=:\n\t" \
                 "mbarrier.try_wait.parity.shared.b64 P, [%0], %1;\n\t" \
                 "@!P bra WL%=;\n\t}" :: "r"(addr), "r"(ph) : "memory")
#define BULK_G2S(dst, src, bytes, mbar) \
    asm volatile("cp.async.bulk.shared::cluster.global.mbarrier::complete_tx::bytes " \
                 "[%0], [%1], %2, [%3];" \
                 :: "r"(dst), "l"(src), "r"(bytes), "r"(mbar) : "memory")

// ---------------- prep: norms + padded bf16 split images --------------------
// split layout: [chunk][split][row 0..127][dim 0..71(pad)]  (pad stays zero)
__device__ __align__(16) unsigned short g_bsplit[NCHUNK * 3 * 128 * 72];
__device__ __align__(16) float2 g_pairs[KTOT];    // (en2, einv)

__global__ void vq_prep(const float* __restrict__ cbk) {
    int idx = blockIdx.x * blockDim.x + threadIdx.x;   // 0 .. KTOT*D-1
    if (idx >= KTOT * D) return;
    int code = idx >> 6, d = idx & 63;
    int c = code >> 7, r = code & 127;
    float x = cbk[idx];
    __nv_bfloat16 b0 = __float2bfloat16(x);
    float r1 = x - __bfloat162float(b0);
    __nv_bfloat16 b1 = __float2bfloat16(r1);
    float r2 = r1 - __bfloat162float(b1);
    __nv_bfloat16 b2 = __float2bfloat16(r2);
    unsigned basei = (unsigned)(c * 3) * 9216u + (unsigned)r * 72u + (unsigned)d;
    g_bsplit[basei]          = __bfloat16_as_ushort(b0);
    g_bsplit[basei + 9216u]  = __bfloat16_as_ushort(b1);
    g_bsplit[basei + 18432u] = __bfloat16_as_ushort(b2);

    if (idx < KTOT) {
        const float4* row = reinterpret_cast<const float4*>(cbk + (size_t)idx * D);
        float s = 0.f;
#pragma unroll
        for (int i = 0; i < D / 4; ++i) {
            float4 v = row[i];
            s += v.x * v.x + v.y * v.y + v.z * v.z + v.w * v.w;
        }
        g_pairs[idx] = make_float2(s, rsqrtf(s));
    }
}

// ---------------- main kernel ------------------------------------------------
__global__ void __launch_bounds__(THREADS, 1)
vq_mma_kernel(const float* __restrict__ z,
              const float* __restrict__ cbk,
              float* __restrict__ e_out,
              float* __restrict__ zq_out,
              float* __restrict__ sim_out,
              float* __restrict__ loss_out) {
    extern __shared__ unsigned char smp[];
    unsigned base;
    asm("{ .reg .u64 t; cvta.to.shared.u64 t, %1; cvt.u32.u64 %0, t; }"
        : "=r"(base) : "l"((void*)smp));

    const int tid   = threadIdx.x;
    const int lane  = tid & 31;
    const int warp  = tid >> 5;
    const int quad  = lane >> 2;     // 0..7
    const int qlane = lane & 3;      // 0..3
    const int mgrp  = warp & 3;      // token row group (32 rows)
    const int ncol  = warp >> 2;     // 32-code column group

    float*  znorms = (float*)(smp + OFF_ZN);
    float*  zinvs  = (float*)(smp + OFF_ZI);
    float*  mindS  = (float*)(smp + OFF_MD);   // [4][128]
    int*    miniS  = (int*)(smp + OFF_MI);     // [4][128]
    const unsigned fullB  = base + OFF_MBAR;        // full0..2
    const unsigned emptyB = fullB + 24;              // empty0..2

    if (tid == 0) {
#pragma unroll
        for (int i = 0; i < NBUF; ++i) {
            MBAR_INIT(fullB + 8u * i, 1);
            MBAR_INIT(emptyB + 8u * i, THREADS);
        }
    }
    __syncthreads();

    // ---- single-thread bulk loads of B chunks 0..2 ----------------------
    if (tid == 0) {
        const char* gb = (const char*)g_bsplit;
#pragma unroll
        for (int i = 0; i < NBUF; ++i) {
            MBAR_EXPECT_TX(fullB + 8u * i, CHUNK_B);
            BULK_G2S(base + OFF_B + i * CHUNK_B, gb + (size_t)i * CHUNK_B,
                     CHUNK_B, fullB + 8u * i);
        }
    }

    // ---- build A split tiles (thread t<128 owns token-row t) ------------
    if (tid < BM) {
        const size_t tok = (size_t)blockIdx.x * BM + tid;
        const float4* zr = reinterpret_cast<const float4*>(z + tok * D);
        float zn = 0.f;
#pragma unroll
        for (int q = 0; q < 16; ++q) {
            float4 v = zr[q];
            zn += v.x * v.x + v.y * v.y + v.z * v.z + v.w * v.w;
            float xs[4] = {v.x, v.y, v.z, v.w};
            unsigned long long p0 = 0, p1 = 0, p2 = 0;
#pragma unroll
            for (int j = 0; j < 4; ++j) {
                float x = xs[j];
                __nv_bfloat16 b0 = __float2bfloat16(x);
                float rr1 = x - __bfloat162float(b0);
                __nv_bfloat16 b1 = __float2bfloat16(rr1);
                float rr2 = rr1 - __bfloat162float(b1);
                __nv_bfloat16 b2 = __float2bfloat16(rr2);
                p0 |= (unsigned long long)__bfloat16_as_ushort(b0) << (16 * j);
                p1 |= (unsigned long long)__bfloat16_as_ushort(b1) << (16 * j);
                p2 |= (unsigned long long)__bfloat16_as_ushort(b2) << (16 * j);
            }
            unsigned off = (unsigned)tid * ROWB + (unsigned)q * 8u;
            *(unsigned long long*)(smp + OFF_A + 0 * SPLIT_B + off) = p0;
            *(unsigned long long*)(smp + OFF_A + 1 * SPLIT_B + off) = p1;
            *(unsigned long long*)(smp + OFF_A + 2 * SPLIT_B + off) = p2;
        }
        znorms[tid] = zn;
        zinvs[tid]  = rsqrtf(zn);
    }
    __syncthreads();     // A tiles + norms visible to all warps

    // this thread's 4 token rows: mi in {0,1}, rowpair in {0,1}
    int rows[2][2];
    float znr[2][2], zir[2][2];
    float* simP[2][2];
#pragma unroll
    for (int mi = 0; mi < 2; ++mi)
#pragma unroll
        for (int rp = 0; rp < 2; ++rp) {
            int r = mgrp * 32 + mi * 16 + rp * 8 + quad;
            rows[mi][rp] = r;
            znr[mi][rp] = znorms[r];
            zir[mi][rp] = zinvs[r];
            simP[mi][rp] = sim_out + ((size_t)blockIdx.x * BM + r) * (size_t)KTOT;
        }

    float mind[2][2] = {{3.4e38f, 3.4e38f}, {3.4e38f, 3.4e38f}};
    int   mini[2][2] = {{0, 0}, {0, 0}};

    // per-lane ldmatrix offsets
    const unsigned aoff = (unsigned)(lane & 15) * ROWB + (unsigned)((lane >> 4) & 1) * 16u;
    const unsigned aBase0 = base + OFF_A + (unsigned)(mgrp * 32) * ROWB + aoff;
    const unsigned boff = ((unsigned)(lane & 7) + (unsigned)((lane >> 4) & 1) * 8u) * ROWB
                        + (unsigned)((lane >> 3) & 1) * 16u;
    const unsigned bColOff = (unsigned)(ncol * 32) * ROWB + boff;

    int buf = 0;
#pragma unroll 1
    for (int c = 0; c < NCHUNK; ++c) {
        const unsigned ph = (unsigned)((c / NBUF) & 1);
        const unsigned fb = fullB + 8u * (unsigned)buf;
        const unsigned eb = emptyB + 8u * (unsigned)buf;

        // ---- prefetch (en2, einv) pairs from global (hidden by MMAs) ----
        const int cbase = c * BN + ncol * 32;
        float4 pv[4];
#pragma unroll
        for (int nj = 0; nj < 4; ++nj)
            pv[nj] = __ldg(reinterpret_cast<const float4*>(
                g_pairs + cbase + nj * 8 + qlane * 2));

        MBAR_WAIT(fb, ph);

        const unsigned Bb = base + OFF_B + (unsigned)buf * CHUNK_B + bColOff;

        float acc[2][4][4];      // [mi][nj][quad-frag]
#pragma unroll
        for (int mi = 0; mi < 2; ++mi)
#pragma unroll
            for (int nj = 0; nj < 4; ++nj)
#pragma unroll
                for (int j = 0; j < 4; ++j) acc[mi][nj][j] = 0.f;

#pragma unroll
        for (int kk = 0; kk < 4; ++kk) {
            uint32_t A[2][3][4];   // [mi][split][frag]
#pragma unroll
            for (int mi = 0; mi < 2; ++mi)
#pragma unroll
                for (int s = 0; s < 3; ++s)
                    ldsm_x4(A[mi][s], aBase0 + (unsigned)(mi * 16) * ROWB
                                      + (unsigned)s * SPLIT_B + (unsigned)kk * 32u);

#pragma unroll
            for (int sb = 0; sb < 3; ++sb) {
                uint32_t Bf[2][4];   // [n16-group][frag]
#pragma unroll
                for (int g = 0; g < 2; ++g)
                    ldsm_x4(Bf[g], Bb + (unsigned)sb * SPLIT_B
                                   + (unsigned)(g * 16) * ROWB + (unsigned)kk * 32u);

                const int nsa = (sb == 0) ? 3 : (sb == 1) ? 2 : 1;
#pragma unroll
                for (int sa = 0; sa < 3; ++sa) {
                    if (sa < nsa) {
#pragma unroll
                        for (int mi = 0; mi < 2; ++mi)
#pragma unroll
                            for (int g = 0; g < 2; ++g) {
                                mma16816(acc[mi][2 * g],     A[mi][sa], &Bf[g][0]);
                                mma16816(acc[mi][2 * g + 1], A[mi][sa], &Bf[g][2]);
                            }
                    }
                }
            }
        }

        // done reading buffer -> signal empty (no block barrier)
        MBAR_ARRIVE(eb);

        // producer: refill this buffer with chunk c+3 once all warps released it
        if (c + NBUF < NCHUNK && tid == 0) {
            MBAR_WAIT(eb, ph);
            const char* gb = (const char*)g_bsplit + (size_t)(c + NBUF) * CHUNK_B;
            MBAR_EXPECT_TX(fb, CHUNK_B);
            BULK_G2S(base + OFF_B + (unsigned)buf * CHUNK_B, gb, CHUNK_B, fb);
        }

        // ---- epilogue from registers (overlaps other warps' MMAs) -------
#pragma unroll
        for (int nj = 0; nj < 4; ++nj) {
            const int gci = cbase + nj * 8 + qlane * 2;
#pragma unroll
            for (int mi = 0; mi < 2; ++mi) {
                const float d00 = acc[mi][nj][0], d01 = acc[mi][nj][1];
                const float d10 = acc[mi][nj][2], d11 = acc[mi][nj][3];
                float t;
                t = fmaf(-2.f, d00, znr[mi][0]) + pv[nj].x;
                if (t < mind[mi][0]) { mind[mi][0] = t; mini[mi][0] = gci; }
                t = fmaf(-2.f, d01, znr[mi][0]) + pv[nj].z;
                if (t < mind[mi][0]) { mind[mi][0] = t; mini[mi][0] = gci + 1; }
                t = fmaf(-2.f, d10, znr[mi][1]) + pv[nj].x;
                if (t < mind[mi][1]) { mind[mi][1] = t; mini[mi][1] = gci; }
                t = fmaf(-2.f, d11, znr[mi][1]) + pv[nj].z;
                if (t < mind[mi][1]) { mind[mi][1] = t; mini[mi][1] = gci + 1; }
                __stcs(reinterpret_cast<float2*>(simP[mi][0] + gci),
                       make_float2(d00 * zir[mi][0] * pv[nj].y, d01 * zir[mi][0] * pv[nj].w));
                __stcs(reinterpret_cast<float2*>(simP[mi][1] + gci),
                       make_float2(d10 * zir[mi][1] * pv[nj].y, d11 * zir[mi][1] * pv[nj].w));
            }
        }

        buf = (buf == NBUF - 1) ? 0 : buf + 1;
    }

    // ---- argmin reduce across qlane (lanes differ in bits 0..1) ---------
#pragma unroll
    for (int mi = 0; mi < 2; ++mi)
#pragma unroll
        for (int rp = 0; rp < 2; ++rp) {
            float d = mind[mi][rp];
            int   i = mini[mi][rp];
#pragma unroll
            for (int off = 1; off <= 2; off <<= 1) {
                float od = __shfl_xor_sync(0xffffffffu, d, off);
                int   oi = __shfl_xor_sync(0xffffffffu, i, off);
                if (od < d || (od == d && oi < i)) { d = od; i = oi; }
            }
            if (qlane == 0) {
                mindS[ncol * 128 + rows[mi][rp]] = d;
                miniS[ncol * 128 + rows[mi][rp]] = i;
            }
        }
    __syncthreads();

    // ---- final per-token outputs: e, z_q, loss (fp32 from global) ------
    if (tid < BM) {
        float bd = mindS[tid];
        int   bi = miniS[tid];
#pragma unroll
        for (int s = 1; s < 4; ++s) {
            float d = mindS[s * 128 + tid];
            int   i = miniS[s * 128 + tid];
            if (d < bd || (d == bd && i < bi)) { bd = d; bi = i; }
        }
        const size_t tok = (size_t)blockIdx.x * BM + tid;
        const float4* er = reinterpret_cast<const float4*>(cbk + (size_t)bi * D);
        const float4* zr = reinterpret_cast<const float4*>(z + tok * D);
        float4* zq = reinterpret_cast<float4*>(zq_out + tok * D);
        float s = 0.f;
#pragma unroll
        for (int q = 0; q < 16; ++q) {
            float4 ev = er[q];
            float4 zv = zr[q];
            float dx = zv.x - ev.x, dy = zv.y - ev.y, dz = zv.z - ev.z, dw = zv.w - ev.w;
            s += dx * dx + dy * dy + dz * dz + dw * dw;
            zq[q] = ev;
        }
        loss_out[tok] = 1.25f * sqrtf(s);
        e_out[tok]    = (float)bi;
    }
}

extern "C" void kernel_launch(void* const* d_in, const int* in_sizes, int n_in,
                              void* d_out, int out_size) {
    const float* z   = (const float*)d_in[0];
    const float* cbk = (const float*)d_in[1];
    const int NT = in_sizes[0] / D;    // 131072

    float* out      = (float*)d_out;
    float* e_out    = out;
    float* zq_out   = e_out + NT;
    float* sim_out  = zq_out + (size_t)NT * D;
    float* loss_out = sim_out + (size_t)NT * KTOT;

    vq_prep<<<(KTOT * D + 255) / 256, 256>>>(cbk);

    cudaFuncSetAttribute(vq_mma_kernel, cudaFuncAttributeMaxDynamicSharedMemorySize, SMEM_REQ);
    vq_mma_kernel<<<NT / BM, THREADS, SMEM_REQ>>>(z, cbk, e_out, zq_out, sim_out, loss_out);
}

// round 14
// speedup vs baseline: 1.6306x; 1.4614x over previous
#include <cuda_runtime.h>
#include <cuda_fp16.h>
#include <cstdint>
#include <cstddef>

// ---------------------------------------------------------------------------
// VQ quantizer via mma.sync (HMMA) fp16 DOUBLE-split GEMM (fp32-accurate dot:
// fp16 has 11 mantissa bits -> 2 splits + 3 cross products ~= 2^-22 error).
// M32xN32 warp tiles; ldmatrix loads; TMA bulk streaming; full/empty mbarrier
// pipeline (warps desync).
//   z (NT x 64) vs codebook (1024 x 64)
//   outputs (concat f32): e[NT], z_q[NT*64], sim[NT*K], loss[NT]
//   16 warps: warp = (mgrp 0..3) x (ncol 0..3); M=32 x N=32 per warp
// ---------------------------------------------------------------------------

#define D        64
#define BM       128                 // tokens per CTA
#define BN       128                 // codes per chunk
#define KTOT     1024
#define NCHUNK   (KTOT / BN)         // 8
#define THREADS  512

#define ROWB     144u                // padded row: 64 fp16 (128B) + 16B pad
#define SPLIT_B  (128u * ROWB)       // 18432 B per split tile
#define CHUNK_B  (2u * SPLIT_B)      // 36864 B per chunk (2 splits)

#define OFF_A    0u                  // A splits: 2 x 18432 = 36864
#define OFF_B0   36864u              // B buffer 0
#define OFF_B1   73728u              // B buffer 1
#define OFF_PAIR 110592u             // 8192 B: (en2, einv) float2 per code
#define OFF_ZN   118784u             // 512 B
#define OFF_ZI   119296u             // 512 B
#define OFF_MD   119808u             // 4 x 128 f32 = 2048
#define OFF_MI   121856u             // 4 x 128 int = 2048
#define OFF_MBAR 123904u             // full0, full1, empty0, empty1
#define SMEM_REQ 123968u

__device__ __forceinline__ void ldsm_x4(uint32_t* r, unsigned addr) {
    asm volatile("ldmatrix.sync.aligned.m8n8.x4.shared.b16 {%0,%1,%2,%3}, [%4];"
                 : "=r"(r[0]), "=r"(r[1]), "=r"(r[2]), "=r"(r[3]) : "r"(addr));
}

__device__ __forceinline__ void mma16816(float* d, const uint32_t* a, const uint32_t* b) {
    asm volatile(
        "mma.sync.aligned.m16n8k16.row.col.f32.f16.f16.f32 "
        "{%0,%1,%2,%3}, {%4,%5,%6,%7}, {%8,%9}, {%0,%1,%2,%3};"
        : "+f"(d[0]), "+f"(d[1]), "+f"(d[2]), "+f"(d[3])
        : "r"(a[0]), "r"(a[1]), "r"(a[2]), "r"(a[3]), "r"(b[0]), "r"(b[1]));
}

#define MBAR_INIT(addr, cnt) \
    asm volatile("mbarrier.init.shared.b64 [%0], %1;" :: "r"(addr), "r"(cnt) : "memory")
#define MBAR_EXPECT_TX(addr, bytes) \
    asm volatile("mbarrier.arrive.expect_tx.shared.b64 _, [%0], %1;" \
                 :: "r"(addr), "r"(bytes) : "memory")
#define MBAR_ARRIVE(addr) \
    asm volatile("mbarrier.arrive.shared.b64 _, [%0];" :: "r"(addr) : "memory")
#define MBAR_WAIT(addr, ph) \
    asm volatile("{\n\t.reg .pred P;\n\tWL%=:\n\t" \
                 "mbarrier.try_wait.parity.shared.b64 P, [%0], %1;\n\t" \
                 "@!P bra WL%=;\n\t}" :: "r"(addr), "r"(ph) : "memory")
#define BULK_G2S(dst, src, bytes, mbar) \
    asm volatile("cp.async.bulk.shared::cluster.global.mbarrier::complete_tx::bytes " \
                 "[%0], [%1], %2, [%3];" \
                 :: "r"(dst), "l"(src), "r"(bytes), "r"(mbar) : "memory")

// ---------------- prep: norms + padded fp16 split images --------------------
// split layout: [chunk][split 0..1][row 0..127][dim 0..71(pad)]  (pad zero)
__device__ __align__(16) unsigned short g_bsplit[NCHUNK * 2 * 128 * 72];
__device__ __align__(16) float2 g_pairs[KTOT];    // (en2, einv)

__global__ void vq_prep(const float* __restrict__ cbk) {
    int idx = blockIdx.x * blockDim.x + threadIdx.x;   // 0 .. KTOT*D-1
    if (idx >= KTOT * D) return;
    int code = idx >> 6, d = idx & 63;
    int c = code >> 7, r = code & 127;
    float x = cbk[idx];
    __half h0 = __float2half_rn(x);
    float r1 = x - __half2float(h0);
    __half h1 = __float2half_rn(r1);
    unsigned basei = (unsigned)(c * 2) * 9216u + (unsigned)r * 72u + (unsigned)d;
    g_bsplit[basei]         = __half_as_ushort(h0);
    g_bsplit[basei + 9216u] = __half_as_ushort(h1);

    if (idx < KTOT) {
        const float4* row = reinterpret_cast<const float4*>(cbk + (size_t)idx * D);
        float s = 0.f;
#pragma unroll
        for (int i = 0; i < D / 4; ++i) {
            float4 v = row[i];
            s += v.x * v.x + v.y * v.y + v.z * v.z + v.w * v.w;
        }
        g_pairs[idx] = make_float2(s, rsqrtf(s));
    }
}

// ---------------- main kernel ------------------------------------------------
__global__ void __launch_bounds__(THREADS, 1)
vq_mma_kernel(const float* __restrict__ z,
              const float* __restrict__ cbk,
              float* __restrict__ e_out,
              float* __restrict__ zq_out,
              float* __restrict__ sim_out,
              float* __restrict__ loss_out) {
    extern __shared__ unsigned char smp[];
    unsigned base;
    asm("{ .reg .u64 t; cvta.to.shared.u64 t, %1; cvt.u32.u64 %0, t; }"
        : "=r"(base) : "l"((void*)smp));

    const int tid   = threadIdx.x;
    const int lane  = tid & 31;
    const int warp  = tid >> 5;
    const int quad  = lane >> 2;     // 0..7
    const int qlane = lane & 3;      // 0..3
    const int mgrp  = warp & 3;      // token row group (32 rows)
    const int ncol  = warp >> 2;     // 32-code column group

    float2* pairs  = (float2*)(smp + OFF_PAIR);
    float*  znorms = (float*)(smp + OFF_ZN);
    float*  zinvs  = (float*)(smp + OFF_ZI);
    float*  mindS  = (float*)(smp + OFF_MD);   // [4][128]
    int*    miniS  = (int*)(smp + OFF_MI);     // [4][128]
    const unsigned full0  = base + OFF_MBAR;
    const unsigned full1  = full0 + 8;
    const unsigned empty0 = full0 + 16;
    const unsigned empty1 = full0 + 24;

    if (tid == 0) {
        MBAR_INIT(full0, 1);  MBAR_INIT(full1, 1);
        MBAR_INIT(empty0, THREADS); MBAR_INIT(empty1, THREADS);
    }
    __syncthreads();

    // ---- single-thread bulk loads of B chunks 0 and 1 -------------------
    if (tid == 0) {
        const char* gb = (const char*)g_bsplit;
        MBAR_EXPECT_TX(full0, CHUNK_B);
        BULK_G2S(base + OFF_B0, gb, CHUNK_B, full0);
        MBAR_EXPECT_TX(full1, CHUNK_B);
        BULK_G2S(base + OFF_B1, gb + CHUNK_B, CHUNK_B, full1);
    }

    // ---- (en2, einv) pair table into smem --------------------------------
    for (int k = tid; k < KTOT; k += THREADS) pairs[k] = g_pairs[k];

    // ---- build A split tiles (thread t<128 owns token-row t) ------------
    if (tid < BM) {
        const size_t tok = (size_t)blockIdx.x * BM + tid;
        const float4* zr = reinterpret_cast<const float4*>(z + tok * D);
        float zn = 0.f;
#pragma unroll
        for (int q = 0; q < 16; ++q) {
            float4 v = zr[q];
            zn += v.x * v.x + v.y * v.y + v.z * v.z + v.w * v.w;
            float xs[4] = {v.x, v.y, v.z, v.w};
            unsigned long long p0 = 0, p1 = 0;
#pragma unroll
            for (int j = 0; j < 4; ++j) {
                float x = xs[j];
                __half h0 = __float2half_rn(x);
                float rr1 = x - __half2float(h0);
                __half h1 = __float2half_rn(rr1);
                p0 |= (unsigned long long)__half_as_ushort(h0) << (16 * j);
                p1 |= (unsigned long long)__half_as_ushort(h1) << (16 * j);
            }
            unsigned off = (unsigned)tid * ROWB + (unsigned)q * 8u;
            *(unsigned long long*)(smp + OFF_A + 0 * SPLIT_B + off) = p0;
            *(unsigned long long*)(smp + OFF_A + 1 * SPLIT_B + off) = p1;
        }
        znorms[tid] = zn;
        zinvs[tid]  = rsqrtf(zn);
    }
    __syncthreads();     // A tiles + norms visible to all warps

    // this thread's 4 token rows: mi in {0,1}, rowpair in {0,1}
    int rows[2][2];
    float znr[2][2], zir[2][2];
    float* simP[2][2];
#pragma unroll
    for (int mi = 0; mi < 2; ++mi)
#pragma unroll
        for (int rp = 0; rp < 2; ++rp) {
            int r = mgrp * 32 + mi * 16 + rp * 8 + quad;
            rows[mi][rp] = r;
            znr[mi][rp] = znorms[r];
            zir[mi][rp] = zinvs[r];
            simP[mi][rp] = sim_out + ((size_t)blockIdx.x * BM + r) * (size_t)KTOT;
        }

    float mind[2][2] = {{3.4e38f, 3.4e38f}, {3.4e38f, 3.4e38f}};
    int   mini[2][2] = {{0, 0}, {0, 0}};

    // per-lane ldmatrix offsets
    const unsigned aoff = (unsigned)(lane & 15) * ROWB + (unsigned)((lane >> 4) & 1) * 16u;
    const unsigned aBase0 = base + OFF_A + (unsigned)(mgrp * 32) * ROWB + aoff;
    const unsigned boff = ((unsigned)(lane & 7) + (unsigned)((lane >> 4) & 1) * 8u) * ROWB
                        + (unsigned)((lane >> 3) & 1) * 16u;
    const unsigned bColOff = (unsigned)(ncol * 32) * ROWB + boff;

#pragma unroll 1
    for (int c = 0; c < NCHUNK; ++c) {
        const int b = c & 1;
        const unsigned ph = (unsigned)((c >> 1) & 1);
        MBAR_WAIT(b ? full1 : full0, ph);

        const unsigned Bb = base + (b ? OFF_B1 : OFF_B0) + bColOff;

        float acc[2][4][4];      // [mi][nj][quad-frag]
#pragma unroll
        for (int mi = 0; mi < 2; ++mi)
#pragma unroll
            for (int nj = 0; nj < 4; ++nj)
#pragma unroll
                for (int j = 0; j < 4; ++j) acc[mi][nj][j] = 0.f;

#pragma unroll
        for (int kk = 0; kk < 4; ++kk) {
            uint32_t A[2][2][4];   // [mi][split][frag]
#pragma unroll
            for (int mi = 0; mi < 2; ++mi)
#pragma unroll
                for (int s = 0; s < 2; ++s)
                    ldsm_x4(A[mi][s], aBase0 + (unsigned)(mi * 16) * ROWB
                                      + (unsigned)s * SPLIT_B + (unsigned)kk * 32u);

#pragma unroll
            for (int sb = 0; sb < 2; ++sb) {
                uint32_t Bf[2][4];   // [n16-group][frag]
#pragma unroll
                for (int g = 0; g < 2; ++g)
                    ldsm_x4(Bf[g], Bb + (unsigned)sb * SPLIT_B
                                   + (unsigned)(g * 16) * ROWB + (unsigned)kk * 32u);

                // products: (sa,sb) in {(0,0),(1,0),(0,1)}  (drop a1b1 ~ 2^-22)
                const int nsa = (sb == 0) ? 2 : 1;
#pragma unroll
                for (int sa = 0; sa < 2; ++sa) {
                    if (sa < nsa) {
#pragma unroll
                        for (int mi = 0; mi < 2; ++mi)
#pragma unroll
                            for (int g = 0; g < 2; ++g) {
                                mma16816(acc[mi][2 * g],     A[mi][sa], &Bf[g][0]);
                                mma16816(acc[mi][2 * g + 1], A[mi][sa], &Bf[g][2]);
                            }
                    }
                }
            }
        }

        // done reading buffer b -> signal empty (no block barrier)
        MBAR_ARRIVE(b ? empty1 : empty0);

        // producer: refill buffer b with chunk c+2 once all warps released it
        if (c + 2 < NCHUNK && tid == 0) {
            MBAR_WAIT(b ? empty1 : empty0, ph);
            const char* gb = (const char*)g_bsplit + (size_t)(c + 2) * CHUNK_B;
            MBAR_EXPECT_TX(b ? full1 : full0, CHUNK_B);
            BULK_G2S(base + (b ? OFF_B1 : OFF_B0), gb, CHUNK_B, b ? full1 : full0);
        }

        // ---- epilogue from registers (overlaps other warps' MMAs) -------
        const int cbase = c * BN + ncol * 32;
#pragma unroll
        for (int nj = 0; nj < 4; ++nj) {
            const int gci = cbase + nj * 8 + qlane * 2;
            float4 pv = *reinterpret_cast<const float4*>(pairs + gci);
#pragma unroll
            for (int mi = 0; mi < 2; ++mi) {
                const float d00 = acc[mi][nj][0], d01 = acc[mi][nj][1];
                const float d10 = acc[mi][nj][2], d11 = acc[mi][nj][3];
                float t;
                t = fmaf(-2.f, d00, znr[mi][0]) + pv.x;
                if (t < mind[mi][0]) { mind[mi][0] = t; mini[mi][0] = gci; }
                t = fmaf(-2.f, d01, znr[mi][0]) + pv.z;
                if (t < mind[mi][0]) { mind[mi][0] = t; mini[mi][0] = gci + 1; }
                t = fmaf(-2.f, d10, znr[mi][1]) + pv.x;
                if (t < mind[mi][1]) { mind[mi][1] = t; mini[mi][1] = gci; }
                t = fmaf(-2.f, d11, znr[mi][1]) + pv.z;
                if (t < mind[mi][1]) { mind[mi][1] = t; mini[mi][1] = gci + 1; }
                __stcs(reinterpret_cast<float2*>(simP[mi][0] + gci),
                       make_float2(d00 * zir[mi][0] * pv.y, d01 * zir[mi][0] * pv.w));
                __stcs(reinterpret_cast<float2*>(simP[mi][1] + gci),
                       make_float2(d10 * zir[mi][1] * pv.y, d11 * zir[mi][1] * pv.w));
            }
        }
    }

    // ---- argmin reduce across qlane (lanes differ in bits 0..1) ---------
#pragma unroll
    for (int mi = 0; mi < 2; ++mi)
#pragma unroll
        for (int rp = 0; rp < 2; ++rp) {
            float d = mind[mi][rp];
            int   i = mini[mi][rp];
#pragma unroll
            for (int off = 1; off <= 2; off <<= 1) {
                float od = __shfl_xor_sync(0xffffffffu, d, off);
                int   oi = __shfl_xor_sync(0xffffffffu, i, off);
                if (od < d || (od == d && oi < i)) { d = od; i = oi; }
            }
            if (qlane == 0) {
                mindS[ncol * 128 + rows[mi][rp]] = d;
                miniS[ncol * 128 + rows[mi][rp]] = i;
            }
        }
    __syncthreads();

    // ---- final per-token outputs: e, z_q, loss (fp32 from global) ------
    if (tid < BM) {
        float bd = mindS[tid];
        int   bi = miniS[tid];
#pragma unroll
        for (int s = 1; s < 4; ++s) {
            float d = mindS[s * 128 + tid];
            int   i = miniS[s * 128 + tid];
            if (d < bd || (d == bd && i < bi)) { bd = d; bi = i; }
        }
        const size_t tok = (size_t)blockIdx.x * BM + tid;
        const float4* er = reinterpret_cast<const float4*>(cbk + (size_t)bi * D);
        const float4* zr = reinterpret_cast<const float4*>(z + tok * D);
        float4* zq = reinterpret_cast<float4*>(zq_out + tok * D);
        float s = 0.f;
#pragma unroll
        for (int q = 0; q < 16; ++q) {
            float4 ev = er[q];
            float4 zv = zr[q];
            float dx = zv.x - ev.x, dy = zv.y - ev.y, dz = zv.z - ev.z, dw = zv.w - ev.w;
            s += dx * dx + dy * dy + dz * dz + dw * dw;
            zq[q] = ev;
        }
        loss_out[tok] = 1.25f * sqrtf(s);
        e_out[tok]    = (float)bi;
    }
}

extern "C" void kernel_launch(void* const* d_in, const int* in_sizes, int n_in,
                              void* d_out, int out_size) {
    const float* z   = (const float*)d_in[0];
    const float* cbk = (const float*)d_in[1];
    const int NT = in_sizes[0] / D;    // 131072

    float* out      = (float*)d_out;
    float* e_out    = out;
    float* zq_out   = e_out + NT;
    float* sim_out  = zq_out + (size_t)NT * D;
    float* loss_out = sim_out + (size_t)NT * KTOT;

    vq_prep<<<(KTOT * D + 255) / 256, 256>>>(cbk);

    cudaFuncSetAttribute(vq_mma_kernel, cudaFuncAttributeMaxDynamicSharedMemorySize, SMEM_REQ);
    vq_mma_kernel<<<NT / BM, THREADS, SMEM_REQ>>>(z, cbk, e_out, zq_out, sim_out, loss_out);
}

// round 15
// speedup vs baseline: 1.7164x; 1.0526x over previous
#include <cuda_runtime.h>
#include <cuda_fp16.h>
#include <cstdint>
#include <cstddef>

// ---------------------------------------------------------------------------
// VQ quantizer via mma.sync (HMMA) fp16 double-split GEMM (fp32-accurate dot).
// 8 warps, M32xN64 warp tiles, A fragments HOISTED into registers for the
// whole kernel (loaded once); B via ldmatrix + TMA bulk double buffer with
// full/empty mbarrier pipeline.
//   z (NT x 64) vs codebook (1024 x 64)
//   outputs (concat f32): e[NT], z_q[NT*64], sim[NT*K], loss[NT]
// ---------------------------------------------------------------------------

#define D        64
#define BM       128                 // tokens per CTA
#define BN       128                 // codes per chunk
#define KTOT     1024
#define NCHUNK   (KTOT / BN)         // 8
#define THREADS  256

#define ROWB     144u                // padded row: 64 fp16 (128B) + 16B pad
#define SPLIT_B  (128u * ROWB)       // 18432 B per split tile
#define CHUNK_B  (2u * SPLIT_B)      // 36864 B per chunk (2 splits)

#define OFF_A    0u                  // A splits: 2 x 18432 = 36864
#define OFF_B0   36864u
#define OFF_B1   73728u
#define OFF_PAIR 110592u             // 8192 B: (en2, einv) float2 per code
#define OFF_ZN   118784u             // 512 B
#define OFF_ZI   119296u             // 512 B
#define OFF_MD   119808u             // 2 x 128 f32 = 1024
#define OFF_MI   120832u             // 2 x 128 int = 1024
#define OFF_MBAR 121856u             // full0, full1, empty0, empty1
#define SMEM_REQ 121920u

__device__ __forceinline__ void ldsm_x4(uint32_t* r, unsigned addr) {
    asm volatile("ldmatrix.sync.aligned.m8n8.x4.shared.b16 {%0,%1,%2,%3}, [%4];"
                 : "=r"(r[0]), "=r"(r[1]), "=r"(r[2]), "=r"(r[3]) : "r"(addr));
}

__device__ __forceinline__ void mma16816(float* d, const uint32_t* a, const uint32_t* b) {
    asm volatile(
        "mma.sync.aligned.m16n8k16.row.col.f32.f16.f16.f32 "
        "{%0,%1,%2,%3}, {%4,%5,%6,%7}, {%8,%9}, {%0,%1,%2,%3};"
        : "+f"(d[0]), "+f"(d[1]), "+f"(d[2]), "+f"(d[3])
        : "r"(a[0]), "r"(a[1]), "r"(a[2]), "r"(a[3]), "r"(b[0]), "r"(b[1]));
}

#define MBAR_INIT(addr, cnt) \
    asm volatile("mbarrier.init.shared.b64 [%0], %1;" :: "r"(addr), "r"(cnt) : "memory")
#define MBAR_EXPECT_TX(addr, bytes) \
    asm volatile("mbarrier.arrive.expect_tx.shared.b64 _, [%0], %1;" \
                 :: "r"(addr), "r"(bytes) : "memory")
#define MBAR_ARRIVE(addr) \
    asm volatile("mbarrier.arrive.shared.b64 _, [%0];" :: "r"(addr) : "memory")
#define MBAR_WAIT(addr, ph) \
    asm volatile("{\n\t.reg .pred P;\n\tWL%=:\n\t" \
                 "mbarrier.try_wait.parity.shared.b64 P, [%0], %1;\n\t" \
                 "@!P bra WL%=;\n\t}" :: "r"(addr), "r"(ph) : "memory")
#define BULK_G2S(dst, src, bytes, mbar) \
    asm volatile("cp.async.bulk.shared::cluster.global.mbarrier::complete_tx::bytes " \
                 "[%0], [%1], %2, [%3];" \
                 :: "r"(dst), "l"(src), "r"(bytes), "r"(mbar) : "memory")

// ---------------- prep: norms + padded fp16 split images --------------------
__device__ __align__(16) unsigned short g_bsplit[NCHUNK * 2 * 128 * 72];
__device__ __align__(16) float2 g_pairs[KTOT];    // (en2, einv)

__global__ void vq_prep(const float* __restrict__ cbk) {
    int idx = blockIdx.x * blockDim.x + threadIdx.x;   // 0 .. KTOT*D-1
    if (idx >= KTOT * D) return;
    int code = idx >> 6, d = idx & 63;
    int c = code >> 7, r = code & 127;
    float x = cbk[idx];
    __half h0 = __float2half_rn(x);
    float r1 = x - __half2float(h0);
    __half h1 = __float2half_rn(r1);
    unsigned basei = (unsigned)(c * 2) * 9216u + (unsigned)r * 72u + (unsigned)d;
    g_bsplit[basei]         = __half_as_ushort(h0);
    g_bsplit[basei + 9216u] = __half_as_ushort(h1);

    if (idx < KTOT) {
        const float4* row = reinterpret_cast<const float4*>(cbk + (size_t)idx * D);
        float s = 0.f;
#pragma unroll
        for (int i = 0; i < D / 4; ++i) {
            float4 v = row[i];
            s += v.x * v.x + v.y * v.y + v.z * v.z + v.w * v.w;
        }
        g_pairs[idx] = make_float2(s, rsqrtf(s));
    }
}

// ---------------- main kernel ------------------------------------------------
__global__ void __launch_bounds__(THREADS, 1)
vq_mma_kernel(const float* __restrict__ z,
              const float* __restrict__ cbk,
              float* __restrict__ e_out,
              float* __restrict__ zq_out,
              float* __restrict__ sim_out,
              float* __restrict__ loss_out) {
    extern __shared__ unsigned char smp[];
    unsigned base;
    asm("{ .reg .u64 t; cvta.to.shared.u64 t, %1; cvt.u32.u64 %0, t; }"
        : "=r"(base) : "l"((void*)smp));

    const int tid   = threadIdx.x;
    const int lane  = tid & 31;
    const int warp  = tid >> 5;
    const int quad  = lane >> 2;     // 0..7
    const int qlane = lane & 3;      // 0..3
    const int mgrp  = warp & 3;      // token row group (32 rows)
    const int ncol  = warp >> 2;     // 0..1: 64-code column group

    float2* pairs  = (float2*)(smp + OFF_PAIR);
    float*  znorms = (float*)(smp + OFF_ZN);
    float*  zinvs  = (float*)(smp + OFF_ZI);
    float*  mindS  = (float*)(smp + OFF_MD);   // [2][128]
    int*    miniS  = (int*)(smp + OFF_MI);     // [2][128]
    const unsigned full0  = base + OFF_MBAR;
    const unsigned full1  = full0 + 8;
    const unsigned empty0 = full0 + 16;
    const unsigned empty1 = full0 + 24;

    if (tid == 0) {
        MBAR_INIT(full0, 1);  MBAR_INIT(full1, 1);
        MBAR_INIT(empty0, THREADS); MBAR_INIT(empty1, THREADS);
    }
    __syncthreads();

    // ---- single-thread bulk loads of B chunks 0 and 1 -------------------
    if (tid == 0) {
        const char* gb = (const char*)g_bsplit;
        MBAR_EXPECT_TX(full0, CHUNK_B);
        BULK_G2S(base + OFF_B0, gb, CHUNK_B, full0);
        MBAR_EXPECT_TX(full1, CHUNK_B);
        BULK_G2S(base + OFF_B1, gb + CHUNK_B, CHUNK_B, full1);
    }

    // ---- (en2, einv) pair table into smem --------------------------------
    for (int k = tid; k < KTOT; k += THREADS) pairs[k] = g_pairs[k];

    // ---- build A split tiles (thread t<128 owns token-row t) ------------
    if (tid < BM) {
        const size_t tok = (size_t)blockIdx.x * BM + tid;
        const float4* zr = reinterpret_cast<const float4*>(z + tok * D);
        float zn = 0.f;
#pragma unroll
        for (int q = 0; q < 16; ++q) {
            float4 v = zr[q];
            zn += v.x * v.x + v.y * v.y + v.z * v.z + v.w * v.w;
            float xs[4] = {v.x, v.y, v.z, v.w};
            unsigned long long p0 = 0, p1 = 0;
#pragma unroll
            for (int j = 0; j < 4; ++j) {
                float x = xs[j];
                __half h0 = __float2half_rn(x);
                float rr1 = x - __half2float(h0);
                __half h1 = __float2half_rn(rr1);
                p0 |= (unsigned long long)__half_as_ushort(h0) << (16 * j);
                p1 |= (unsigned long long)__half_as_ushort(h1) << (16 * j);
            }
            unsigned off = (unsigned)tid * ROWB + (unsigned)q * 8u;
            *(unsigned long long*)(smp + OFF_A + 0 * SPLIT_B + off) = p0;
            *(unsigned long long*)(smp + OFF_A + 1 * SPLIT_B + off) = p1;
        }
        znorms[tid] = zn;
        zinvs[tid]  = rsqrtf(zn);
    }
    __syncthreads();     // A tiles + norms visible to all warps

    // ---- HOIST: load all A fragments ONCE into registers ----------------
    const unsigned aoff = (unsigned)(lane & 15) * ROWB + (unsigned)((lane >> 4) & 1) * 16u;
    const unsigned aBase0 = base + OFF_A + (unsigned)(mgrp * 32) * ROWB + aoff;
    uint32_t A[2][2][4][4];        // [mi][split][kk][frag]
#pragma unroll
    for (int mi = 0; mi < 2; ++mi)
#pragma unroll
        for (int s = 0; s < 2; ++s)
#pragma unroll
            for (int kk = 0; kk < 4; ++kk)
                ldsm_x4(A[mi][s][kk], aBase0 + (unsigned)(mi * 16) * ROWB
                                      + (unsigned)s * SPLIT_B + (unsigned)kk * 32u);

    // this thread's 4 token rows: mi in {0,1}, rowpair in {0,1}
    int rows[2][2];
    float znr[2][2], zir[2][2];
    float* simP[2][2];
#pragma unroll
    for (int mi = 0; mi < 2; ++mi)
#pragma unroll
        for (int rp = 0; rp < 2; ++rp) {
            int r = mgrp * 32 + mi * 16 + rp * 8 + quad;
            rows[mi][rp] = r;
            znr[mi][rp] = znorms[r];
            zir[mi][rp] = zinvs[r];
            simP[mi][rp] = sim_out + ((size_t)blockIdx.x * BM + r) * (size_t)KTOT;
        }

    float mind[2][2] = {{3.4e38f, 3.4e38f}, {3.4e38f, 3.4e38f}};
    int   mini[2][2] = {{0, 0}, {0, 0}};

    const unsigned boff = ((unsigned)(lane & 7) + (unsigned)((lane >> 4) & 1) * 8u) * ROWB
                        + (unsigned)((lane >> 3) & 1) * 16u;
    const unsigned bColOff = (unsigned)(ncol * 64) * ROWB + boff;

#pragma unroll 1
    for (int c = 0; c < NCHUNK; ++c) {
        const int b = c & 1;
        const unsigned ph = (unsigned)((c >> 1) & 1);
        MBAR_WAIT(b ? full1 : full0, ph);

        const unsigned Bb = base + (b ? OFF_B1 : OFF_B0) + bColOff;

        float acc[2][8][4];      // [mi][nj (8 x n8)][quad-frag]
#pragma unroll
        for (int mi = 0; mi < 2; ++mi)
#pragma unroll
            for (int nj = 0; nj < 8; ++nj)
#pragma unroll
                for (int j = 0; j < 4; ++j) acc[mi][nj][j] = 0.f;

#pragma unroll
        for (int kk = 0; kk < 4; ++kk) {
#pragma unroll
            for (int sb = 0; sb < 2; ++sb) {
                uint32_t Bf[4][4];   // [n16-group 0..3][frag]
#pragma unroll
                for (int g = 0; g < 4; ++g)
                    ldsm_x4(Bf[g], Bb + (unsigned)sb * SPLIT_B
                                   + (unsigned)(g * 16) * ROWB + (unsigned)kk * 32u);

                // products: (sa,sb) in {(0,0),(1,0),(0,1)}  (drop a1b1 ~ 2^-22)
                const int nsa = (sb == 0) ? 2 : 1;
#pragma unroll
                for (int sa = 0; sa < 2; ++sa) {
                    if (sa < nsa) {
#pragma unroll
                        for (int mi = 0; mi < 2; ++mi)
#pragma unroll
                            for (int g = 0; g < 4; ++g) {
                                mma16816(acc[mi][2 * g],     A[mi][sa][kk], &Bf[g][0]);
                                mma16816(acc[mi][2 * g + 1], A[mi][sa][kk], &Bf[g][2]);
                            }
                    }
                }
            }
        }

        // done reading buffer b -> signal empty (no block barrier)
        MBAR_ARRIVE(b ? empty1 : empty0);

        // producer: refill buffer b with chunk c+2 once all warps released it
        if (c + 2 < NCHUNK && tid == 0) {
            MBAR_WAIT(b ? empty1 : empty0, ph);
            const char* gb = (const char*)g_bsplit + (size_t)(c + 2) * CHUNK_B;
            MBAR_EXPECT_TX(b ? full1 : full0, CHUNK_B);
            BULK_G2S(base + (b ? OFF_B1 : OFF_B0), gb, CHUNK_B, b ? full1 : full0);
        }

        // ---- epilogue from registers (overlaps other warps' MMAs) -------
        const int cbase = c * BN + ncol * 64;
#pragma unroll
        for (int nj = 0; nj < 8; ++nj) {
            const int gci = cbase + nj * 8 + qlane * 2;
            float4 pv = *reinterpret_cast<const float4*>(pairs + gci);
#pragma unroll
            for (int mi = 0; mi < 2; ++mi) {
                const float d00 = acc[mi][nj][0], d01 = acc[mi][nj][1];
                const float d10 = acc[mi][nj][2], d11 = acc[mi][nj][3];
                float t;
                t = fmaf(-2.f, d00, znr[mi][0]) + pv.x;
                if (t < mind[mi][0]) { mind[mi][0] = t; mini[mi][0] = gci; }
                t = fmaf(-2.f, d01, znr[mi][0]) + pv.z;
                if (t < mind[mi][0]) { mind[mi][0] = t; mini[mi][0] = gci + 1; }
                t = fmaf(-2.f, d10, znr[mi][1]) + pv.x;
                if (t < mind[mi][1]) { mind[mi][1] = t; mini[mi][1] = gci; }
                t = fmaf(-2.f, d11, znr[mi][1]) + pv.z;
                if (t < mind[mi][1]) { mind[mi][1] = t; mini[mi][1] = gci + 1; }
                __stcs(reinterpret_cast<float2*>(simP[mi][0] + gci),
                       make_float2(d00 * zir[mi][0] * pv.y, d01 * zir[mi][0] * pv.w));
                __stcs(reinterpret_cast<float2*>(simP[mi][1] + gci),
                       make_float2(d10 * zir[mi][1] * pv.y, d11 * zir[mi][1] * pv.w));
            }
        }
    }

    // ---- argmin reduce across qlane (lanes differ in bits 0..1) ---------
#pragma unroll
    for (int mi = 0; mi < 2; ++mi)
#pragma unroll
        for (int rp = 0; rp < 2; ++rp) {
            float d = mind[mi][rp];
            int   i = mini[mi][rp];
#pragma unroll
            for (int off = 1; off <= 2; off <<= 1) {
                float od = __shfl_xor_sync(0xffffffffu, d, off);
                int   oi = __shfl_xor_sync(0xffffffffu, i, off);
                if (od < d || (od == d && oi < i)) { d = od; i = oi; }
            }
            if (qlane == 0) {
                mindS[ncol * 128 + rows[mi][rp]] = d;
                miniS[ncol * 128 + rows[mi][rp]] = i;
            }
        }
    __syncthreads();

    // ---- final per-token outputs: e, z_q, loss (fp32 from global) ------
    if (tid < BM) {
        float bd = mindS[tid];
        int   bi = miniS[tid];
        {
            float d = mindS[128 + tid];
            int   i = miniS[128 + tid];
            if (d < bd || (d == bd && i < bi)) { bd = d; bi = i; }
        }
        const size_t tok = (size_t)blockIdx.x * BM + tid;
        const float4* er = reinterpret_cast<const float4*>(cbk + (size_t)bi * D);
        const float4* zr = reinterpret_cast<const float4*>(z + tok * D);
        float4* zq = reinterpret_cast<float4*>(zq_out + tok * D);
        float s = 0.f;
#pragma unroll
        for (int q = 0; q < 16; ++q) {
            float4 ev = er[q];
            float4 zv = zr[q];
            float dx = zv.x - ev.x, dy = zv.y - ev.y, dz = zv.z - ev.z, dw = zv.w - ev.w;
            s += dx * dx + dy * dy + dz * dz + dw * dw;
            zq[q] = ev;
        }
        loss_out[tok] = 1.25f * sqrtf(s);
        e_out[tok]    = (float)bi;
    }
}

extern "C" void kernel_launch(void* const* d_in, const int* in_sizes, int n_in,
                              void* d_out, int out_size) {
    const float* z   = (const float*)d_in[0];
    const float* cbk = (const float*)d_in[1];
    const int NT = in_sizes[0] / D;    // 131072

    float* out      = (float*)d_out;
    float* e_out    = out;
    float* zq_out   = e_out + NT;
    float* sim_out  = zq_out + (size_t)NT * D;
    float* loss_out = sim_out + (size_t)NT * KTOT;

    vq_prep<<<(KTOT * D + 255) / 256, 256>>>(cbk);

    cudaFuncSetAttribute(vq_mma_kernel, cudaFuncAttributeMaxDynamicSharedMemorySize, SMEM_REQ);
    vq_mma_kernel<<<NT / BM, THREADS, SMEM_REQ>>>(z, cbk, e_out, zq_out, sim_out, loss_out);
}